// round 14
// baseline (speedup 1.0000x reference)
#include <cuda_runtime.h>
#include <cuda_fp16.h>
#include <cstdint>

// Problem dims
constexpr int B_ = 16, S_ = 4096, D_ = 512, M_ = 2048;
constexpr int NROWS = B_ * S_;   // 65536
constexpr int NQK   = 2 * D_;    // 1024 (q and k only; v never materialized)

// ---------------------------------------------------------------------------
// Scratch (device globals: no allocations allowed)
// ---------------------------------------------------------------------------
__device__ __half g_xh[(size_t)NROWS * D_];        // x in fp16
__device__ __half g_wh[(size_t)NQK * D_];          // W_qk^T fp16 [n][k]
__device__ float g_u[B_ * D_];                     // W_k @ q_last
__device__ float g_c[B_];                          // q_last . b_k
__device__ float g_scores[NROWS];
__device__ float g_part[B_ * 32 * D_];             // chunk partials (unnorm)
__device__ float g_cmx[B_ * 32];                   // chunk max
__device__ float g_csum[B_ * 32];                  // chunk sum(exp)
__device__ float g_h[B_ * D_];
__device__ float g_h1[B_ * M_];
__device__ float g_m2p[4][B_ * M_];                // mlp2 k-split partials

// ---------------------------------------------------------------------------
// Helpers (baseline PTX: ldmatrix / mma.sync / cp.async — sm_80+)
// ---------------------------------------------------------------------------
__device__ __forceinline__ uint32_t smem_u32(const void* p) {
    uint32_t a;
    asm("{ .reg .u64 t; cvta.to.shared.u64 t, %1; cvt.u32.u64 %0, t; }"
        : "=r"(a) : "l"(p));
    return a;
}

// Swizzle<3,4,3> for 128-byte rows: bits[6:4] ^= bits[9:7]
#define SWZ128(o) ((o) ^ ((((uint32_t)(o)) >> 3) & 0x70u))

__device__ __forceinline__ void cp_async16(uint32_t sdst, const void* gsrc) {
    asm volatile("cp.async.cg.shared.global [%0], [%1], 16;"
                 :: "r"(sdst), "l"(gsrc) : "memory");
}
#define CP_COMMIT() asm volatile("cp.async.commit_group;" ::: "memory")
#define CP_WAIT(n)  asm volatile("cp.async.wait_group %0;" :: "n"(n) : "memory")

__device__ __forceinline__ void ldm_x4(uint32_t* r, uint32_t addr) {
    asm volatile("ldmatrix.sync.aligned.m8n8.x4.shared.b16 {%0,%1,%2,%3}, [%4];"
                 : "=r"(r[0]), "=r"(r[1]), "=r"(r[2]), "=r"(r[3]) : "r"(addr));
}

__device__ __forceinline__ void mma_f32acc(float* c, const uint32_t* a, const uint32_t* b) {
    asm volatile(
        "mma.sync.aligned.m16n8k16.row.col.f32.f16.f16.f32 "
        "{%0,%1,%2,%3}, {%4,%5,%6,%7}, {%8,%9}, {%0,%1,%2,%3};"
        : "+f"(c[0]), "+f"(c[1]), "+f"(c[2]), "+f"(c[3])
        : "r"(a[0]), "r"(a[1]), "r"(a[2]), "r"(a[3]), "r"(b[0]), "r"(b[1]));
}

// ---------------------------------------------------------------------------
// qlast + u fused (fp32 exact, one block per batch):
//  ql[d] = x[b,S-1] @ W_q + b_q ; c = ql.b_k ; u[j] = W_k[j,:].ql
// ---------------------------------------------------------------------------
__global__ __launch_bounds__(512)
void qlast_u_kernel(const float* __restrict__ x, const float* __restrict__ W,
                    const float* __restrict__ bq)
{
    __shared__ float xs[D_];
    __shared__ float ql[D_];
    __shared__ float red[D_];
    const int b = blockIdx.x, d = threadIdx.x;
    const int warp = d >> 5, lane = d & 31;

    xs[d] = x[((size_t)b * S_ + (S_ - 1)) * D_ + d];
    __syncthreads();

    float acc = bq[d];
    #pragma unroll 8
    for (int k = 0; k < D_; k++) acc = fmaf(xs[k], W[(size_t)k * 1536 + d], acc);
    ql[d] = acc;
    red[d] = acc * bq[512 + d];
    __syncthreads();

    for (int s = 256; s; s >>= 1) {
        if (d < s) red[d] += red[d + s];
        __syncthreads();
    }
    if (d == 0) g_c[b] = red[0];

    // u: 16 warps x 32 rows each, lanes over k (coalesced)
    for (int jj = 0; jj < 32; jj++) {
        const int j = warp * 32 + jj;
        const float* wrow = W + (size_t)j * 1536 + 512;
        float a2 = 0.f;
        #pragma unroll
        for (int i = 0; i < 16; i++)
            a2 = fmaf(wrow[lane + i * 32], ql[lane + i * 32], a2);
        #pragma unroll
        for (int off = 16; off; off >>= 1) a2 += __shfl_xor_sync(0xffffffffu, a2, off);
        if (lane == 0) g_u[b * D_ + j] = a2;
    }
}

// ---------------------------------------------------------------------------
// scores + x->fp16 + W->fp16 fusion
// ---------------------------------------------------------------------------
__global__ void scores_cvt_kernel(const float* __restrict__ x,
                                  const float* __restrict__ W)
{
    const int gtid = blockIdx.x * 256 + threadIdx.x;
    if (gtid < D_ * NQK) {
        const int k = gtid >> 10, n = gtid & 1023;
        g_wh[(size_t)n * D_ + k] = __float2half_rn(W[(size_t)k * 1536 + n]);
    }

    const int gw   = (blockIdx.x * blockDim.x + threadIdx.x) >> 5;
    const int lane = threadIdx.x & 31;
    const int b    = gw >> 12;

    const float4* ur = (const float4*)(g_u + b * D_);
    const float4* xr = (const float4*)(x + (size_t)gw * D_);
    __half2* xo = (__half2*)(g_xh + (size_t)gw * D_);

    float acc = 0.f;
    #pragma unroll
    for (int it = 0; it < 4; it++) {
        const int e4 = lane + it * 32;
        float4 uv = ur[e4];
        float4 xv = xr[e4];
        acc += uv.x * xv.x + uv.y * xv.y + uv.z * xv.z + uv.w * xv.w;
        __half2 h0 = __halves2half2(__float2half_rn(xv.x), __float2half_rn(xv.y));
        __half2 h1 = __halves2half2(__float2half_rn(xv.z), __float2half_rn(xv.w));
        xo[e4 * 2]     = h0;
        xo[e4 * 2 + 1] = h1;
    }
    #pragma unroll
    for (int off = 16; off; off >>= 1) acc += __shfl_xor_sync(0xffffffffu, acc, off);
    if (lane == 0) g_scores[gw] = acc + g_c[b];
}

// ---------------------------------------------------------------------------
// QK GEMM (round-12 config): CTA 128x128, warp 64x32, TK=64, 3-stage
// ---------------------------------------------------------------------------
constexpr int TM = 128, TN = 128, TK = 64;
constexpr int NCHUNK = D_ / TK;  // 8
constexpr int A_TILE = 128 * 128;
constexpr int B_TILE = 128 * 128;
constexpr int OFF_AH = 0;
constexpr int OFF_BH = OFF_AH + A_TILE;
constexpr int STAGE_BYTES = OFF_BH + B_TILE;           // 32 KB
constexpr int QKV_SMEM    = 3 * STAGE_BYTES;           // 96 KB dynamic

__global__ __launch_bounds__(256, 2)
void qk_mma(const float* __restrict__ bias,
            float* __restrict__ q_out, float* __restrict__ k_out)
{
    extern __shared__ __align__(128) uint8_t sm[];
    const uint32_t sb = smem_u32(sm);

    const int tid  = threadIdx.x;
    const int warp = tid >> 5, lane = tid & 31;
    const int n0 = blockIdx.x * TN;
    const int m0 = blockIdx.y * TM;
    const int wm = (warp & 1) * 64;
    const int wn = (warp >> 1) * 32;

    const int rl = tid >> 3;
    const int cl = tid & 7;

    auto load_stage = [&](int stage, int ch) {
        const uint32_t s0 = sb + stage * STAGE_BYTES;
        const int kcol = ch * TK + cl * 8;
        #pragma unroll
        for (int j = 0; j < 4; j++) {
            const int row = rl + j * 32;
            const uint32_t so = SWZ128((uint32_t)row * 128 + cl * 16);
            cp_async16(s0 + OFF_AH + so, g_xh + (size_t)(m0 + row) * D_ + kcol);
            cp_async16(s0 + OFF_BH + so, g_wh + (size_t)(n0 + row) * D_ + kcol);
        }
    };

    float acc[4][4][4];
    #pragma unroll
    for (int i = 0; i < 4; i++)
        #pragma unroll
        for (int j = 0; j < 4; j++)
            #pragma unroll
            for (int e = 0; e < 4; e++) acc[i][j][e] = 0.f;

    const uint32_t a_row = (lane & 15);
    const uint32_t a_byt = (lane >> 4) << 4;
    const uint32_t b_row = ((lane >> 4) << 3) + (lane & 7);
    const uint32_t b_byt = ((lane >> 3) & 1) << 4;

    load_stage(0, 0); CP_COMMIT();
    load_stage(1, 1); CP_COMMIT();

    for (int ch = 0; ch < NCHUNK; ch++) {
        if (ch + 2 < NCHUNK) {
            load_stage((ch + 2) % 3, ch + 2); CP_COMMIT();
            CP_WAIT(2);
        } else {
            CP_WAIT(0);
        }
        __syncthreads();

        const uint32_t s0 = sb + (ch % 3) * STAGE_BYTES;

        #pragma unroll
        for (int kk = 0; kk < 4; kk++) {
            uint32_t ah[4][4];
            #pragma unroll
            for (int mf = 0; mf < 4; mf++) {
                const uint32_t ra = SWZ128((uint32_t)(wm + mf * 16 + a_row) * 128
                                           + kk * 32 + a_byt);
                ldm_x4(ah[mf], s0 + OFF_AH + ra);
            }
            uint32_t bh[4][2];
            #pragma unroll
            for (int p = 0; p < 2; p++) {
                const uint32_t rb = SWZ128((uint32_t)(wn + p * 16 + b_row) * 128
                                           + kk * 32 + b_byt);
                uint32_t t[4];
                ldm_x4(t, s0 + OFF_BH + rb);
                bh[p * 2][0] = t[0]; bh[p * 2][1] = t[1];
                bh[p * 2 + 1][0] = t[2]; bh[p * 2 + 1][1] = t[3];
            }
            #pragma unroll
            for (int mf = 0; mf < 4; mf++)
                #pragma unroll
                for (int nf = 0; nf < 4; nf++) mma_f32acc(acc[mf][nf], ah[mf], bh[nf]);
        }
        __syncthreads();
    }

    const int region = n0 >> 9;
    float* dst = region ? k_out : q_out;
    const int cbase = n0 - region * 512;

    #pragma unroll
    for (int mf = 0; mf < 4; mf++) {
        #pragma unroll
        for (int nf = 0; nf < 4; nf++) {
            const int colg = n0 + wn + nf * 8 + (lane & 3) * 2;
            const float2 bv = *(const float2*)(bias + colg);
            const int col = cbase + wn + nf * 8 + (lane & 3) * 2;
            const int r0 = m0 + wm + mf * 16 + (lane >> 2);
            float2 v0 = make_float2(acc[mf][nf][0] + bv.x, acc[mf][nf][1] + bv.y);
            float2 v1 = make_float2(acc[mf][nf][2] + bv.x, acc[mf][nf][3] + bv.y);
            *(float2*)(dst + (size_t)r0 * D_ + col)       = v0;
            *(float2*)(dst + (size_t)(r0 + 8) * D_ + col) = v1;
        }
    }
}

// ---------------------------------------------------------------------------
// y partials with ONLINE softmax per 128-row chunk:
//   mx_c = max(scores), sum_c = sum exp(s-mx_c), part_c[d] = sum exp*x
// ---------------------------------------------------------------------------
__global__ __launch_bounds__(512)
void y_part_kernel(const float* __restrict__ x)
{
    __shared__ float ss[128];
    const int b = blockIdx.x, ch = blockIdx.y, d = threadIdx.x;
    const float* xp = x + ((size_t)b * S_ + ch * 128) * D_ + d;

    if (d < 128) ss[d] = g_scores[(size_t)b * S_ + ch * 128 + d];
    __syncthreads();

    float mx = -1e30f;
    #pragma unroll 16
    for (int s = 0; s < 128; s++) mx = fmaxf(mx, ss[s]);

    float a0 = 0.f, a1 = 0.f, lsum = 0.f;
    #pragma unroll 8
    for (int s = 0; s < 128; s += 2) {
        const float e0 = expf(ss[s]     - mx);
        const float e1 = expf(ss[s + 1] - mx);
        lsum += e0 + e1;
        a0 = fmaf(e0, xp[(size_t)s * D_],       a0);
        a1 = fmaf(e1, xp[(size_t)(s + 1) * D_], a1);
    }
    g_part[(b * 32 + ch) * D_ + d] = a0 + a1;
    if (d == 0) { g_cmx[b * 32 + ch] = mx; g_csum[b * 32 + ch] = lsum; }
}

// h[b] = x[b,S-1] + (merged softmax avg of x) @ W_v + b_v
__global__ __launch_bounds__(512)
void h_kernel(const float* __restrict__ x, const float* __restrict__ W,
              const float* __restrict__ bq)
{
    __shared__ float ys[D_];
    const int b = blockIdx.x, d = threadIdx.x;

    float gmx = -1e30f;
    #pragma unroll
    for (int ch = 0; ch < 32; ch++) gmx = fmaxf(gmx, g_cmx[b * 32 + ch]);
    float gsum = 0.f, yy = 0.f;
    #pragma unroll
    for (int ch = 0; ch < 32; ch++) {
        const float w = expf(g_cmx[b * 32 + ch] - gmx);
        gsum += g_csum[b * 32 + ch] * w;
        yy = fmaf(g_part[(b * 32 + ch) * D_ + d], w, yy);
    }
    ys[d] = yy / gsum;
    __syncthreads();

    float acc = x[((size_t)b * S_ + (S_ - 1)) * D_ + d] + bq[1024 + d];
    #pragma unroll 8
    for (int k = 0; k < D_; k++) acc = fmaf(ys[k], W[(size_t)k * 1536 + 1024 + d], acc);
    g_h[b * D_ + d] = acc;
}

// ---------------------------------------------------------------------------
// MLP layers (fp32), batch-tiled; mlp2 K-split x4; reduce fused into mlp3
// ---------------------------------------------------------------------------
__global__ __launch_bounds__(256)
void mlp1_kernel(const float* __restrict__ W1, const float* __restrict__ b1)
{
    __shared__ float hs[4][D_];
    const int bg = blockIdx.y * 4, tid = threadIdx.x;
    #pragma unroll
    for (int i = 0; i < 8; i++) {
        const int idx = tid + i * 256;
        hs[idx >> 9][idx & 511] = g_h[(bg + (idx >> 9)) * D_ + (idx & 511)];
    }
    __syncthreads();
    const int m = blockIdx.x * 256 + tid;
    float a0 = b1[m], a1 = a0, a2 = a0, a3 = a0;
    #pragma unroll 8
    for (int k = 0; k < D_; k++) {
        const float w = W1[(size_t)k * M_ + m];
        a0 = fmaf(hs[0][k], w, a0);
        a1 = fmaf(hs[1][k], w, a1);
        a2 = fmaf(hs[2][k], w, a2);
        a3 = fmaf(hs[3][k], w, a3);
    }
    g_h1[(bg + 0) * M_ + m] = fmaxf(a0, 0.f);
    g_h1[(bg + 1) * M_ + m] = fmaxf(a1, 0.f);
    g_h1[(bg + 2) * M_ + m] = fmaxf(a2, 0.f);
    g_h1[(bg + 3) * M_ + m] = fmaxf(a3, 0.f);
}

__global__ __launch_bounds__(256)
void mlp2_part_kernel(const float* __restrict__ W2)
{
    __shared__ float hs[4][512];
    const int bg = blockIdx.y * 4, kz = blockIdx.z, tid = threadIdx.x;
    const int k0 = kz * 512;
    #pragma unroll
    for (int i = 0; i < 8; i++) {
        const int idx = tid + i * 256;
        hs[idx >> 9][idx & 511] = g_h1[(bg + (idx >> 9)) * M_ + k0 + (idx & 511)];
    }
    __syncthreads();
    const int m = blockIdx.x * 256 + tid;
    float a0 = 0.f, a1 = 0.f, a2 = 0.f, a3 = 0.f;
    #pragma unroll 8
    for (int k = 0; k < 512; k++) {
        const float w = W2[(size_t)(k0 + k) * M_ + m];
        a0 = fmaf(hs[0][k], w, a0);
        a1 = fmaf(hs[1][k], w, a1);
        a2 = fmaf(hs[2][k], w, a2);
        a3 = fmaf(hs[3][k], w, a3);
    }
    g_m2p[kz][(bg + 0) * M_ + m] = a0;
    g_m2p[kz][(bg + 1) * M_ + m] = a1;
    g_m2p[kz][(bg + 2) * M_ + m] = a2;
    g_m2p[kz][(bg + 3) * M_ + m] = a3;
}

// mlp2 reduce + relu + mlp3 dot, fused: warp w = batch w
__global__ void mlp3_kernel(const float* __restrict__ b2,
                            const float* __restrict__ W3,
                            const float* __restrict__ b3,
                            float* __restrict__ out)
{
    const int w = threadIdx.x >> 5, lane = threadIdx.x & 31;
    float acc = 0.f;
    #pragma unroll
    for (int i = 0; i < M_ / 32; i++) {
        const int m = lane + i * 32;
        const int e = w * M_ + m;
        float v = b2[m] + g_m2p[0][e] + g_m2p[1][e] + g_m2p[2][e] + g_m2p[3][e];
        acc = fmaf(fmaxf(v, 0.f), W3[m], acc);
    }
    #pragma unroll
    for (int off = 16; off; off >>= 1) acc += __shfl_xor_sync(0xffffffffu, acc, off);
    if (lane == 0) out[w] = acc + b3[0];
}

// ---------------------------------------------------------------------------
// Entry. Output layout: (out, q, k) flat: [0,16) out, then q, then k.
// y_part at launch slot 4 -> profiled this round.
// ---------------------------------------------------------------------------
extern "C" void kernel_launch(void* const* d_in, const int* in_sizes, int n_in,
                              void* d_out, int out_size)
{
    const float* x     = (const float*)d_in[0];
    const float* W_qkv = (const float*)d_in[1];
    const float* b_qkv = (const float*)d_in[2];
    const float* W1    = (const float*)d_in[3];
    const float* b1    = (const float*)d_in[4];
    const float* W2    = (const float*)d_in[5];
    const float* b2    = (const float*)d_in[6];
    const float* W3    = (const float*)d_in[7];
    const float* b3    = (const float*)d_in[8];

    float* out   = (float*)d_out;
    float* q_out = out + 16;
    float* k_out = out + 16 + (size_t)NROWS * D_;

    cudaFuncSetAttribute(qk_mma, cudaFuncAttributeMaxDynamicSharedMemorySize, QKV_SMEM);

    qlast_u_kernel<<<B_, 512>>>(x, W_qkv, b_qkv);                   // 1
    scores_cvt_kernel<<<NROWS / 8, 256>>>(x, W_qkv);                // 2
    qk_mma<<<dim3(NQK / TN, NROWS / TM), 256, QKV_SMEM>>>(b_qkv, q_out, k_out); // 3
    y_part_kernel<<<dim3(B_, 32), 512>>>(x);                       // 4 (ncu)
    h_kernel<<<B_, 512>>>(x, W_qkv, b_qkv);                         // 5
    mlp1_kernel<<<dim3(M_ / 256, B_ / 4), 256>>>(W1, b1);           // 6
    mlp2_part_kernel<<<dim3(M_ / 256, B_ / 4, 4), 256>>>(W2);       // 7
    mlp3_kernel<<<1, 512>>>(b2, W3, b3, out);                       // 8
}

// round 15
// speedup vs baseline: 1.0869x; 1.0869x over previous
#include <cuda_runtime.h>
#include <cuda_fp16.h>
#include <cstdint>

// Problem dims
constexpr int B_ = 16, S_ = 4096, D_ = 512, M_ = 2048;
constexpr int NROWS = B_ * S_;   // 65536
constexpr int NQK   = 2 * D_;    // 1024 (q and k only; v never materialized)

// ---------------------------------------------------------------------------
// Scratch (device globals: no allocations allowed)
// ---------------------------------------------------------------------------
__device__ __half g_xh[(size_t)NROWS * D_];        // x in fp16
__device__ __half g_wh[(size_t)NQK * D_];          // W_qk^T fp16 [n][k]
__device__ float g_ql[B_ * D_];                    // q_last (fp32 exact)
__device__ float g_u[B_ * D_];                     // W_k @ q_last
__device__ float g_c[B_];                          // q_last . b_k
__device__ float g_scores[NROWS];
__device__ float g_part[B_ * 32 * D_];             // chunk partials (unnorm)
__device__ float g_cmx[B_ * 32];                   // chunk max
__device__ float g_csum[B_ * 32];                  // chunk sum(exp)
__device__ float g_h[B_ * D_];
__device__ float g_h1[B_ * M_];
__device__ float g_m2p[4][B_ * M_];                // mlp2 k-split partials

// ---------------------------------------------------------------------------
// Helpers (baseline PTX: ldmatrix / mma.sync / cp.async — sm_80+)
// ---------------------------------------------------------------------------
__device__ __forceinline__ uint32_t smem_u32(const void* p) {
    uint32_t a;
    asm("{ .reg .u64 t; cvta.to.shared.u64 t, %1; cvt.u32.u64 %0, t; }"
        : "=r"(a) : "l"(p));
    return a;
}

// Swizzle<3,4,3> for 128-byte rows: bits[6:4] ^= bits[9:7]
#define SWZ128(o) ((o) ^ ((((uint32_t)(o)) >> 3) & 0x70u))

__device__ __forceinline__ void cp_async16(uint32_t sdst, const void* gsrc) {
    asm volatile("cp.async.cg.shared.global [%0], [%1], 16;"
                 :: "r"(sdst), "l"(gsrc) : "memory");
}
#define CP_COMMIT() asm volatile("cp.async.commit_group;" ::: "memory")
#define CP_WAIT(n)  asm volatile("cp.async.wait_group %0;" :: "n"(n) : "memory")

__device__ __forceinline__ void ldm_x4(uint32_t* r, uint32_t addr) {
    asm volatile("ldmatrix.sync.aligned.m8n8.x4.shared.b16 {%0,%1,%2,%3}, [%4];"
                 : "=r"(r[0]), "=r"(r[1]), "=r"(r[2]), "=r"(r[3]) : "r"(addr));
}

__device__ __forceinline__ void mma_f32acc(float* c, const uint32_t* a, const uint32_t* b) {
    asm volatile(
        "mma.sync.aligned.m16n8k16.row.col.f32.f16.f16.f32 "
        "{%0,%1,%2,%3}, {%4,%5,%6,%7}, {%8,%9}, {%0,%1,%2,%3};"
        : "+f"(c[0]), "+f"(c[1]), "+f"(c[2]), "+f"(c[3])
        : "r"(a[0]), "r"(a[1]), "r"(a[2]), "r"(a[3]), "r"(b[0]), "r"(b[1]));
}

// ---------------------------------------------------------------------------
// fp32 exact path (output 0): qlast (16 blocks) + u (1024 blocks, parallel)
// ---------------------------------------------------------------------------
__global__ __launch_bounds__(512)
void qlast_kernel(const float* __restrict__ x, const float* __restrict__ W,
                  const float* __restrict__ bq)
{
    __shared__ float xs[D_];
    __shared__ float red[D_];
    const int b = blockIdx.x, d = threadIdx.x;

    xs[d] = x[((size_t)b * S_ + (S_ - 1)) * D_ + d];
    __syncthreads();

    float acc = bq[d];
    #pragma unroll 8
    for (int k = 0; k < D_; k++) acc = fmaf(xs[k], W[(size_t)k * 1536 + d], acc);
    g_ql[b * D_ + d] = acc;

    red[d] = acc * bq[512 + d];
    __syncthreads();
    for (int s = 256; s; s >>= 1) {
        if (d < s) red[d] += red[d + s];
        __syncthreads();
    }
    if (d == 0) g_c[b] = red[0];
}

// u[b][j] = W_k[j,:] . q_last[b]  — warp per j, lanes over k (1024 blocks)
__global__ __launch_bounds__(256)
void u_kernel(const float* __restrict__ W)
{
    __shared__ float qs[D_];
    const int b = blockIdx.y, tid = threadIdx.x;
    const int warp = tid >> 5, lane = tid & 31;
    qs[tid]       = g_ql[b * D_ + tid];
    qs[tid + 256] = g_ql[b * D_ + tid + 256];
    __syncthreads();

    const int j = blockIdx.x * 8 + warp;
    const float* wrow = W + (size_t)j * 1536 + 512;
    float acc = 0.f;
    #pragma unroll
    for (int i = 0; i < 16; i++)
        acc = fmaf(wrow[lane + i * 32], qs[lane + i * 32], acc);
    #pragma unroll
    for (int off = 16; off; off >>= 1) acc += __shfl_xor_sync(0xffffffffu, acc, off);
    if (lane == 0) g_u[b * D_ + j] = acc;
}

// ---------------------------------------------------------------------------
// scores + x->fp16 + W->fp16 fusion
// ---------------------------------------------------------------------------
__global__ void scores_cvt_kernel(const float* __restrict__ x,
                                  const float* __restrict__ W)
{
    const int gtid = blockIdx.x * 256 + threadIdx.x;
    if (gtid < D_ * NQK) {
        const int k = gtid >> 10, n = gtid & 1023;
        g_wh[(size_t)n * D_ + k] = __float2half_rn(W[(size_t)k * 1536 + n]);
    }

    const int gw   = (blockIdx.x * blockDim.x + threadIdx.x) >> 5;
    const int lane = threadIdx.x & 31;
    const int b    = gw >> 12;

    const float4* ur = (const float4*)(g_u + b * D_);
    const float4* xr = (const float4*)(x + (size_t)gw * D_);
    __half2* xo = (__half2*)(g_xh + (size_t)gw * D_);

    float acc = 0.f;
    #pragma unroll
    for (int it = 0; it < 4; it++) {
        const int e4 = lane + it * 32;
        float4 uv = ur[e4];
        float4 xv = xr[e4];
        acc += uv.x * xv.x + uv.y * xv.y + uv.z * xv.z + uv.w * xv.w;
        __half2 h0 = __halves2half2(__float2half_rn(xv.x), __float2half_rn(xv.y));
        __half2 h1 = __halves2half2(__float2half_rn(xv.z), __float2half_rn(xv.w));
        xo[e4 * 2]     = h0;
        xo[e4 * 2 + 1] = h1;
    }
    #pragma unroll
    for (int off = 16; off; off >>= 1) acc += __shfl_xor_sync(0xffffffffu, acc, off);
    if (lane == 0) g_scores[gw] = acc + g_c[b];
}

// ---------------------------------------------------------------------------
// QK GEMM (round-12 config): CTA 128x128, warp 64x32, TK=64, 3-stage
// ---------------------------------------------------------------------------
constexpr int TM = 128, TN = 128, TK = 64;
constexpr int NCHUNK = D_ / TK;  // 8
constexpr int A_TILE = 128 * 128;
constexpr int B_TILE = 128 * 128;
constexpr int OFF_AH = 0;
constexpr int OFF_BH = OFF_AH + A_TILE;
constexpr int STAGE_BYTES = OFF_BH + B_TILE;           // 32 KB
constexpr int QKV_SMEM    = 3 * STAGE_BYTES;           // 96 KB dynamic

__global__ __launch_bounds__(256, 2)
void qk_mma(const float* __restrict__ bias,
            float* __restrict__ q_out, float* __restrict__ k_out)
{
    extern __shared__ __align__(128) uint8_t sm[];
    const uint32_t sb = smem_u32(sm);

    const int tid  = threadIdx.x;
    const int warp = tid >> 5, lane = tid & 31;
    const int n0 = blockIdx.x * TN;
    const int m0 = blockIdx.y * TM;
    const int wm = (warp & 1) * 64;
    const int wn = (warp >> 1) * 32;

    const int rl = tid >> 3;
    const int cl = tid & 7;

    auto load_stage = [&](int stage, int ch) {
        const uint32_t s0 = sb + stage * STAGE_BYTES;
        const int kcol = ch * TK + cl * 8;
        #pragma unroll
        for (int j = 0; j < 4; j++) {
            const int row = rl + j * 32;
            const uint32_t so = SWZ128((uint32_t)row * 128 + cl * 16);
            cp_async16(s0 + OFF_AH + so, g_xh + (size_t)(m0 + row) * D_ + kcol);
            cp_async16(s0 + OFF_BH + so, g_wh + (size_t)(n0 + row) * D_ + kcol);
        }
    };

    float acc[4][4][4];
    #pragma unroll
    for (int i = 0; i < 4; i++)
        #pragma unroll
        for (int j = 0; j < 4; j++)
            #pragma unroll
            for (int e = 0; e < 4; e++) acc[i][j][e] = 0.f;

    const uint32_t a_row = (lane & 15);
    const uint32_t a_byt = (lane >> 4) << 4;
    const uint32_t b_row = ((lane >> 4) << 3) + (lane & 7);
    const uint32_t b_byt = ((lane >> 3) & 1) << 4;

    load_stage(0, 0); CP_COMMIT();
    load_stage(1, 1); CP_COMMIT();

    for (int ch = 0; ch < NCHUNK; ch++) {
        if (ch + 2 < NCHUNK) {
            load_stage((ch + 2) % 3, ch + 2); CP_COMMIT();
            CP_WAIT(2);
        } else {
            CP_WAIT(0);
        }
        __syncthreads();

        const uint32_t s0 = sb + (ch % 3) * STAGE_BYTES;

        #pragma unroll
        for (int kk = 0; kk < 4; kk++) {
            uint32_t ah[4][4];
            #pragma unroll
            for (int mf = 0; mf < 4; mf++) {
                const uint32_t ra = SWZ128((uint32_t)(wm + mf * 16 + a_row) * 128
                                           + kk * 32 + a_byt);
                ldm_x4(ah[mf], s0 + OFF_AH + ra);
            }
            uint32_t bh[4][2];
            #pragma unroll
            for (int p = 0; p < 2; p++) {
                const uint32_t rb = SWZ128((uint32_t)(wn + p * 16 + b_row) * 128
                                           + kk * 32 + b_byt);
                uint32_t t[4];
                ldm_x4(t, s0 + OFF_BH + rb);
                bh[p * 2][0] = t[0]; bh[p * 2][1] = t[1];
                bh[p * 2 + 1][0] = t[2]; bh[p * 2 + 1][1] = t[3];
            }
            #pragma unroll
            for (int mf = 0; mf < 4; mf++)
                #pragma unroll
                for (int nf = 0; nf < 4; nf++) mma_f32acc(acc[mf][nf], ah[mf], bh[nf]);
        }
        __syncthreads();
    }

    const int region = n0 >> 9;
    float* dst = region ? k_out : q_out;
    const int cbase = n0 - region * 512;

    #pragma unroll
    for (int mf = 0; mf < 4; mf++) {
        #pragma unroll
        for (int nf = 0; nf < 4; nf++) {
            const int colg = n0 + wn + nf * 8 + (lane & 3) * 2;
            const float2 bv = *(const float2*)(bias + colg);
            const int col = cbase + wn + nf * 8 + (lane & 3) * 2;
            const int r0 = m0 + wm + mf * 16 + (lane >> 2);
            float2 v0 = make_float2(acc[mf][nf][0] + bv.x, acc[mf][nf][1] + bv.y);
            float2 v1 = make_float2(acc[mf][nf][2] + bv.x, acc[mf][nf][3] + bv.y);
            *(float2*)(dst + (size_t)r0 * D_ + col)       = v0;
            *(float2*)(dst + (size_t)(r0 + 8) * D_ + col) = v1;
        }
    }
}

// ---------------------------------------------------------------------------
// y partials with ONLINE softmax per 128-row chunk
// ---------------------------------------------------------------------------
__global__ __launch_bounds__(512)
void y_part_kernel(const float* __restrict__ x)
{
    __shared__ float ss[128];
    const int b = blockIdx.x, ch = blockIdx.y, d = threadIdx.x;
    const float* xp = x + ((size_t)b * S_ + ch * 128) * D_ + d;

    if (d < 128) ss[d] = g_scores[(size_t)b * S_ + ch * 128 + d];
    __syncthreads();

    float mx = -1e30f;
    #pragma unroll 16
    for (int s = 0; s < 128; s++) mx = fmaxf(mx, ss[s]);

    float a0 = 0.f, a1 = 0.f, lsum = 0.f;
    #pragma unroll 8
    for (int s = 0; s < 128; s += 2) {
        const float e0 = expf(ss[s]     - mx);
        const float e1 = expf(ss[s + 1] - mx);
        lsum += e0 + e1;
        a0 = fmaf(e0, xp[(size_t)s * D_],       a0);
        a1 = fmaf(e1, xp[(size_t)(s + 1) * D_], a1);
    }
    g_part[(b * 32 + ch) * D_ + d] = a0 + a1;
    if (d == 0) { g_cmx[b * 32 + ch] = mx; g_csum[b * 32 + ch] = lsum; }
}

// h[b] = x[b,S-1] + (merged softmax avg of x) @ W_v + b_v
__global__ __launch_bounds__(512)
void h_kernel(const float* __restrict__ x, const float* __restrict__ W,
              const float* __restrict__ bq)
{
    __shared__ float ys[D_];
    const int b = blockIdx.x, d = threadIdx.x;

    float gmx = -1e30f;
    #pragma unroll
    for (int ch = 0; ch < 32; ch++) gmx = fmaxf(gmx, g_cmx[b * 32 + ch]);
    float gsum = 0.f, yy = 0.f;
    #pragma unroll
    for (int ch = 0; ch < 32; ch++) {
        const float w = expf(g_cmx[b * 32 + ch] - gmx);
        gsum += g_csum[b * 32 + ch] * w;
        yy = fmaf(g_part[(b * 32 + ch) * D_ + d], w, yy);
    }
    ys[d] = yy / gsum;
    __syncthreads();

    float acc = x[((size_t)b * S_ + (S_ - 1)) * D_ + d] + bq[1024 + d];
    #pragma unroll 8
    for (int k = 0; k < D_; k++) acc = fmaf(ys[k], W[(size_t)k * 1536 + 1024 + d], acc);
    g_h[b * D_ + d] = acc;
}

// ---------------------------------------------------------------------------
// MLP layers (fp32), batch-tiled; mlp2 K-split x4; reduce fused into mlp3
// ---------------------------------------------------------------------------
__global__ __launch_bounds__(256)
void mlp1_kernel(const float* __restrict__ W1, const float* __restrict__ b1)
{
    __shared__ float hs[4][D_];
    const int bg = blockIdx.y * 4, tid = threadIdx.x;
    #pragma unroll
    for (int i = 0; i < 8; i++) {
        const int idx = tid + i * 256;
        hs[idx >> 9][idx & 511] = g_h[(bg + (idx >> 9)) * D_ + (idx & 511)];
    }
    __syncthreads();
    const int m = blockIdx.x * 256 + tid;
    float a0 = b1[m], a1 = a0, a2 = a0, a3 = a0;
    #pragma unroll 8
    for (int k = 0; k < D_; k++) {
        const float w = W1[(size_t)k * M_ + m];
        a0 = fmaf(hs[0][k], w, a0);
        a1 = fmaf(hs[1][k], w, a1);
        a2 = fmaf(hs[2][k], w, a2);
        a3 = fmaf(hs[3][k], w, a3);
    }
    g_h1[(bg + 0) * M_ + m] = fmaxf(a0, 0.f);
    g_h1[(bg + 1) * M_ + m] = fmaxf(a1, 0.f);
    g_h1[(bg + 2) * M_ + m] = fmaxf(a2, 0.f);
    g_h1[(bg + 3) * M_ + m] = fmaxf(a3, 0.f);
}

__global__ __launch_bounds__(256)
void mlp2_part_kernel(const float* __restrict__ W2)
{
    __shared__ float hs[4][512];
    const int bg = blockIdx.y * 4, kz = blockIdx.z, tid = threadIdx.x;
    const int k0 = kz * 512;
    #pragma unroll
    for (int i = 0; i < 8; i++) {
        const int idx = tid + i * 256;
        hs[idx >> 9][idx & 511] = g_h1[(bg + (idx >> 9)) * M_ + k0 + (idx & 511)];
    }
    __syncthreads();
    const int m = blockIdx.x * 256 + tid;
    float a0 = 0.f, a1 = 0.f, a2 = 0.f, a3 = 0.f;
    #pragma unroll 8
    for (int k = 0; k < 512; k++) {
        const float w = W2[(size_t)(k0 + k) * M_ + m];
        a0 = fmaf(hs[0][k], w, a0);
        a1 = fmaf(hs[1][k], w, a1);
        a2 = fmaf(hs[2][k], w, a2);
        a3 = fmaf(hs[3][k], w, a3);
    }
    g_m2p[kz][(bg + 0) * M_ + m] = a0;
    g_m2p[kz][(bg + 1) * M_ + m] = a1;
    g_m2p[kz][(bg + 2) * M_ + m] = a2;
    g_m2p[kz][(bg + 3) * M_ + m] = a3;
}

// mlp2 reduce + relu + mlp3 dot, fused: warp w = batch w
__global__ void mlp3_kernel(const float* __restrict__ b2,
                            const float* __restrict__ W3,
                            const float* __restrict__ b3,
                            float* __restrict__ out)
{
    const int w = threadIdx.x >> 5, lane = threadIdx.x & 31;
    float acc = 0.f;
    #pragma unroll
    for (int i = 0; i < M_ / 32; i++) {
        const int m = lane + i * 32;
        const int e = w * M_ + m;
        float v = b2[m] + g_m2p[0][e] + g_m2p[1][e] + g_m2p[2][e] + g_m2p[3][e];
        acc = fmaf(fmaxf(v, 0.f), W3[m], acc);
    }
    #pragma unroll
    for (int off = 16; off; off >>= 1) acc += __shfl_xor_sync(0xffffffffu, acc, off);
    if (lane == 0) out[w] = acc + b3[0];
}

// ---------------------------------------------------------------------------
// Entry. Output layout: (out, q, k) flat: [0,16) out, then q, then k.
// ---------------------------------------------------------------------------
extern "C" void kernel_launch(void* const* d_in, const int* in_sizes, int n_in,
                              void* d_out, int out_size)
{
    const float* x     = (const float*)d_in[0];
    const float* W_qkv = (const float*)d_in[1];
    const float* b_qkv = (const float*)d_in[2];
    const float* W1    = (const float*)d_in[3];
    const float* b1    = (const float*)d_in[4];
    const float* W2    = (const float*)d_in[5];
    const float* b2    = (const float*)d_in[6];
    const float* W3    = (const float*)d_in[7];
    const float* b3    = (const float*)d_in[8];

    float* out   = (float*)d_out;
    float* q_out = out + 16;
    float* k_out = out + 16 + (size_t)NROWS * D_;

    cudaFuncSetAttribute(qk_mma, cudaFuncAttributeMaxDynamicSharedMemorySize, QKV_SMEM);

    qlast_kernel<<<B_, 512>>>(x, W_qkv, b_qkv);                     // 1
    u_kernel<<<dim3(D_ / 8, B_), 256>>>(W_qkv);                     // 2
    scores_cvt_kernel<<<NROWS / 8, 256>>>(x, W_qkv);                // 3
    qk_mma<<<dim3(NQK / TN, NROWS / TM), 256, QKV_SMEM>>>(b_qkv, q_out, k_out); // 4 (ncu)
    y_part_kernel<<<dim3(B_, 32), 512>>>(x);                        // 5
    h_kernel<<<B_, 512>>>(x, W_qkv, b_qkv);                         // 6
    mlp1_kernel<<<dim3(M_ / 256, B_ / 4), 256>>>(W1, b1);           // 7
    mlp2_part_kernel<<<dim3(M_ / 256, B_ / 4, 4), 256>>>(W2);       // 8
    mlp3_kernel<<<1, 512>>>(b2, W3, b3, out);                       // 9
}

// round 16
// speedup vs baseline: 1.2147x; 1.1175x over previous
#include <cuda_runtime.h>
#include <cuda_fp16.h>
#include <cstdint>

// Problem dims
constexpr int B_ = 16, S_ = 4096, D_ = 512, M_ = 2048;
constexpr int NROWS = B_ * S_;   // 65536
constexpr int NQK   = 2 * D_;    // 1024 (q and k only; v never materialized)

// ---------------------------------------------------------------------------
// Scratch (device globals: no allocations allowed)
// ---------------------------------------------------------------------------
__device__ __half g_xh[(size_t)NROWS * D_];        // x in fp16
__device__ __half g_wh[(size_t)NQK * D_];          // W_qk^T fp16 [n][k]
__device__ float g_qlp[4][B_ * D_];                // q_last k-split partials
__device__ float g_u[B_ * D_];                     // W_k @ q_last
__device__ float g_c[B_];                          // q_last . b_k
__device__ float g_scores[NROWS];
__device__ float g_part[B_ * 32 * D_];             // y chunk partials (unnorm)
__device__ float g_cmx[B_ * 32];                   // chunk max
__device__ float g_csum[B_ * 32];                  // chunk sum(exp)
__device__ float g_hp[4][B_ * D_];                 // h k-split partials
__device__ float g_h1[B_ * M_];
__device__ float g_m2p[4][B_ * M_];                // mlp2 k-split partials

// ---------------------------------------------------------------------------
// Helpers (baseline PTX: ldmatrix / mma.sync / cp.async — sm_80+)
// ---------------------------------------------------------------------------
__device__ __forceinline__ uint32_t smem_u32(const void* p) {
    uint32_t a;
    asm("{ .reg .u64 t; cvta.to.shared.u64 t, %1; cvt.u32.u64 %0, t; }"
        : "=r"(a) : "l"(p));
    return a;
}

// Swizzle<3,4,3> for 128-byte rows: bits[6:4] ^= bits[9:7]
#define SWZ128(o) ((o) ^ ((((uint32_t)(o)) >> 3) & 0x70u))

__device__ __forceinline__ void cp_async16(uint32_t sdst, const void* gsrc) {
    asm volatile("cp.async.cg.shared.global [%0], [%1], 16;"
                 :: "r"(sdst), "l"(gsrc) : "memory");
}
#define CP_COMMIT() asm volatile("cp.async.commit_group;" ::: "memory")
#define CP_WAIT(n)  asm volatile("cp.async.wait_group %0;" :: "n"(n) : "memory")

__device__ __forceinline__ void ldm_x4(uint32_t* r, uint32_t addr) {
    asm volatile("ldmatrix.sync.aligned.m8n8.x4.shared.b16 {%0,%1,%2,%3}, [%4];"
                 : "=r"(r[0]), "=r"(r[1]), "=r"(r[2]), "=r"(r[3]) : "r"(addr));
}

__device__ __forceinline__ void mma_f32acc(float* c, const uint32_t* a, const uint32_t* b) {
    asm volatile(
        "mma.sync.aligned.m16n8k16.row.col.f32.f16.f16.f32 "
        "{%0,%1,%2,%3}, {%4,%5,%6,%7}, {%8,%9}, {%0,%1,%2,%3};"
        : "+f"(c[0]), "+f"(c[1]), "+f"(c[2]), "+f"(c[3])
        : "r"(a[0]), "r"(a[1]), "r"(a[2]), "r"(a[3]), "r"(b[0]), "r"(b[1]));
}

// ---------------------------------------------------------------------------
// qlast partials: grid (4, B). Block (kz, b) computes
//   qlp[kz][b][d] = sum_{k in kz-range} x[b,S-1,k] * W_q[k][d]
// ---------------------------------------------------------------------------
__global__ __launch_bounds__(512)
void qlast_part_kernel(const float* __restrict__ x, const float* __restrict__ W)
{
    __shared__ float xs[128];
    const int kz = blockIdx.x, b = blockIdx.y, d = threadIdx.x;
    const int k0 = kz * 128;

    if (d < 128) xs[d] = x[((size_t)b * S_ + (S_ - 1)) * D_ + k0 + d];
    __syncthreads();

    float acc = 0.f;
    #pragma unroll 8
    for (int j = 0; j < 128; j++)
        acc = fmaf(xs[j], W[(size_t)(k0 + j) * 1536 + d], acc);
    g_qlp[kz][b * D_ + d] = acc;
}

// u[b][j] = W_k[j,:] . q_last[b] — warp per j (1024 blocks).
// Combines qlast partials + b_q into smem; block x==0 also emits c[b].
__global__ __launch_bounds__(256)
void u_kernel(const float* __restrict__ W, const float* __restrict__ bq)
{
    __shared__ float qs[D_];
    __shared__ float red[256];
    const int b = blockIdx.y, tid = threadIdx.x;
    const int warp = tid >> 5, lane = tid & 31;

    #pragma unroll
    for (int h = 0; h < 2; h++) {
        const int i = tid + h * 256;
        qs[i] = bq[i] + g_qlp[0][b * D_ + i] + g_qlp[1][b * D_ + i]
                      + g_qlp[2][b * D_ + i] + g_qlp[3][b * D_ + i];
    }
    __syncthreads();

    if (blockIdx.x == 0) {
        red[tid] = qs[tid] * bq[512 + tid] + qs[tid + 256] * bq[512 + tid + 256];
        __syncthreads();
        for (int s = 128; s; s >>= 1) {
            if (tid < s) red[tid] += red[tid + s];
            __syncthreads();
        }
        if (tid == 0) g_c[b] = red[0];
    }

    const int j = blockIdx.x * 8 + warp;
    const float* wrow = W + (size_t)j * 1536 + 512;
    float acc = 0.f;
    #pragma unroll
    for (int i = 0; i < 16; i++)
        acc = fmaf(wrow[lane + i * 32], qs[lane + i * 32], acc);
    #pragma unroll
    for (int off = 16; off; off >>= 1) acc += __shfl_xor_sync(0xffffffffu, acc, off);
    if (lane == 0) g_u[b * D_ + j] = acc;
}

// ---------------------------------------------------------------------------
// scores + x->fp16 + W->fp16 fusion
// ---------------------------------------------------------------------------
__global__ void scores_cvt_kernel(const float* __restrict__ x,
                                  const float* __restrict__ W)
{
    const int gtid = blockIdx.x * 256 + threadIdx.x;
    if (gtid < D_ * NQK) {
        const int k = gtid >> 10, n = gtid & 1023;
        g_wh[(size_t)n * D_ + k] = __float2half_rn(W[(size_t)k * 1536 + n]);
    }

    const int gw   = (blockIdx.x * blockDim.x + threadIdx.x) >> 5;
    const int lane = threadIdx.x & 31;
    const int b    = gw >> 12;

    const float4* ur = (const float4*)(g_u + b * D_);
    const float4* xr = (const float4*)(x + (size_t)gw * D_);
    __half2* xo = (__half2*)(g_xh + (size_t)gw * D_);

    float acc = 0.f;
    #pragma unroll
    for (int it = 0; it < 4; it++) {
        const int e4 = lane + it * 32;
        float4 uv = ur[e4];
        float4 xv = xr[e4];
        acc += uv.x * xv.x + uv.y * xv.y + uv.z * xv.z + uv.w * xv.w;
        __half2 h0 = __halves2half2(__float2half_rn(xv.x), __float2half_rn(xv.y));
        __half2 h1 = __halves2half2(__float2half_rn(xv.z), __float2half_rn(xv.w));
        xo[e4 * 2]     = h0;
        xo[e4 * 2 + 1] = h1;
    }
    #pragma unroll
    for (int off = 16; off; off >>= 1) acc += __shfl_xor_sync(0xffffffffu, acc, off);
    if (lane == 0) g_scores[gw] = acc + g_c[b];
}

// ---------------------------------------------------------------------------
// QK GEMM (round-12 config): CTA 128x128, warp 64x32, TK=64, 3-stage
// ---------------------------------------------------------------------------
constexpr int TM = 128, TN = 128, TK = 64;
constexpr int NCHUNK = D_ / TK;  // 8
constexpr int A_TILE = 128 * 128;
constexpr int B_TILE = 128 * 128;
constexpr int OFF_AH = 0;
constexpr int OFF_BH = OFF_AH + A_TILE;
constexpr int STAGE_BYTES = OFF_BH + B_TILE;           // 32 KB
constexpr int QKV_SMEM    = 3 * STAGE_BYTES;           // 96 KB dynamic

__global__ __launch_bounds__(256, 2)
void qk_mma(const float* __restrict__ bias,
            float* __restrict__ q_out, float* __restrict__ k_out)
{
    extern __shared__ __align__(128) uint8_t sm[];
    const uint32_t sb = smem_u32(sm);

    const int tid  = threadIdx.x;
    const int warp = tid >> 5, lane = tid & 31;
    const int n0 = blockIdx.x * TN;
    const int m0 = blockIdx.y * TM;
    const int wm = (warp & 1) * 64;
    const int wn = (warp >> 1) * 32;

    const int rl = tid >> 3;
    const int cl = tid & 7;

    auto load_stage = [&](int stage, int ch) {
        const uint32_t s0 = sb + stage * STAGE_BYTES;
        const int kcol = ch * TK + cl * 8;
        #pragma unroll
        for (int j = 0; j < 4; j++) {
            const int row = rl + j * 32;
            const uint32_t so = SWZ128((uint32_t)row * 128 + cl * 16);
            cp_async16(s0 + OFF_AH + so, g_xh + (size_t)(m0 + row) * D_ + kcol);
            cp_async16(s0 + OFF_BH + so, g_wh + (size_t)(n0 + row) * D_ + kcol);
        }
    };

    float acc[4][4][4];
    #pragma unroll
    for (int i = 0; i < 4; i++)
        #pragma unroll
        for (int j = 0; j < 4; j++)
            #pragma unroll
            for (int e = 0; e < 4; e++) acc[i][j][e] = 0.f;

    const uint32_t a_row = (lane & 15);
    const uint32_t a_byt = (lane >> 4) << 4;
    const uint32_t b_row = ((lane >> 4) << 3) + (lane & 7);
    const uint32_t b_byt = ((lane >> 3) & 1) << 4;

    load_stage(0, 0); CP_COMMIT();
    load_stage(1, 1); CP_COMMIT();

    for (int ch = 0; ch < NCHUNK; ch++) {
        if (ch + 2 < NCHUNK) {
            load_stage((ch + 2) % 3, ch + 2); CP_COMMIT();
            CP_WAIT(2);
        } else {
            CP_WAIT(0);
        }
        __syncthreads();

        const uint32_t s0 = sb + (ch % 3) * STAGE_BYTES;

        #pragma unroll
        for (int kk = 0; kk < 4; kk++) {
            uint32_t ah[4][4];
            #pragma unroll
            for (int mf = 0; mf < 4; mf++) {
                const uint32_t ra = SWZ128((uint32_t)(wm + mf * 16 + a_row) * 128
                                           + kk * 32 + a_byt);
                ldm_x4(ah[mf], s0 + OFF_AH + ra);
            }
            uint32_t bh[4][2];
            #pragma unroll
            for (int p = 0; p < 2; p++) {
                const uint32_t rb = SWZ128((uint32_t)(wn + p * 16 + b_row) * 128
                                           + kk * 32 + b_byt);
                uint32_t t[4];
                ldm_x4(t, s0 + OFF_BH + rb);
                bh[p * 2][0] = t[0]; bh[p * 2][1] = t[1];
                bh[p * 2 + 1][0] = t[2]; bh[p * 2 + 1][1] = t[3];
            }
            #pragma unroll
            for (int mf = 0; mf < 4; mf++)
                #pragma unroll
                for (int nf = 0; nf < 4; nf++) mma_f32acc(acc[mf][nf], ah[mf], bh[nf]);
        }
        __syncthreads();
    }

    const int region = n0 >> 9;
    float* dst = region ? k_out : q_out;
    const int cbase = n0 - region * 512;

    #pragma unroll
    for (int mf = 0; mf < 4; mf++) {
        #pragma unroll
        for (int nf = 0; nf < 4; nf++) {
            const int colg = n0 + wn + nf * 8 + (lane & 3) * 2;
            const float2 bv = *(const float2*)(bias + colg);
            const int col = cbase + wn + nf * 8 + (lane & 3) * 2;
            const int r0 = m0 + wm + mf * 16 + (lane >> 2);
            float2 v0 = make_float2(acc[mf][nf][0] + bv.x, acc[mf][nf][1] + bv.y);
            float2 v1 = make_float2(acc[mf][nf][2] + bv.x, acc[mf][nf][3] + bv.y);
            *(float2*)(dst + (size_t)r0 * D_ + col)       = v0;
            *(float2*)(dst + (size_t)(r0 + 8) * D_ + col) = v1;
        }
    }
}

// ---------------------------------------------------------------------------
// y partials with ONLINE softmax per 128-row chunk
// ---------------------------------------------------------------------------
__global__ __launch_bounds__(512)
void y_part_kernel(const float* __restrict__ x)
{
    __shared__ float ss[128];
    const int b = blockIdx.x, ch = blockIdx.y, d = threadIdx.x;
    const float* xp = x + ((size_t)b * S_ + ch * 128) * D_ + d;

    if (d < 128) ss[d] = g_scores[(size_t)b * S_ + ch * 128 + d];
    __syncthreads();

    float mx = -1e30f;
    #pragma unroll 16
    for (int s = 0; s < 128; s++) mx = fmaxf(mx, ss[s]);

    float a0 = 0.f, a1 = 0.f, lsum = 0.f;
    #pragma unroll 8
    for (int s = 0; s < 128; s += 2) {
        const float e0 = expf(ss[s]     - mx);
        const float e1 = expf(ss[s + 1] - mx);
        lsum += e0 + e1;
        a0 = fmaf(e0, xp[(size_t)s * D_],       a0);
        a1 = fmaf(e1, xp[(size_t)(s + 1) * D_], a1);
    }
    g_part[(b * 32 + ch) * D_ + d] = a0 + a1;
    if (d == 0) { g_cmx[b * 32 + ch] = mx; g_csum[b * 32 + ch] = lsum; }
}

// ---------------------------------------------------------------------------
// h partials: grid (4, B). Block (kz, b):
//   merge softmax stats; ys[j] for its 128-k slice; partial GEMV over W_v rows
// ---------------------------------------------------------------------------
__global__ __launch_bounds__(512)
void h_part_kernel(const float* __restrict__ W)
{
    __shared__ float ys[128];
    const int kz = blockIdx.x, b = blockIdx.y, d = threadIdx.x;
    const int k0 = kz * 128;

    float gmx = -1e30f;
    #pragma unroll
    for (int ch = 0; ch < 32; ch++) gmx = fmaxf(gmx, g_cmx[b * 32 + ch]);
    float gsum = 0.f;
    #pragma unroll
    for (int ch = 0; ch < 32; ch++)
        gsum += g_csum[b * 32 + ch] * expf(g_cmx[b * 32 + ch] - gmx);

    if (d < 128) {
        float yy = 0.f;
        #pragma unroll
        for (int ch = 0; ch < 32; ch++) {
            const float w = expf(g_cmx[b * 32 + ch] - gmx);
            yy = fmaf(g_part[(b * 32 + ch) * D_ + k0 + d], w, yy);
        }
        ys[d] = yy / gsum;
    }
    __syncthreads();

    float acc = 0.f;
    #pragma unroll 8
    for (int j = 0; j < 128; j++)
        acc = fmaf(ys[j], W[(size_t)(k0 + j) * 1536 + 1024 + d], acc);
    g_hp[kz][b * D_ + d] = acc;
}

// ---------------------------------------------------------------------------
// MLP layers (fp32), batch-tiled; h combine folded into mlp1 staging
// ---------------------------------------------------------------------------
__global__ __launch_bounds__(256)
void mlp1_kernel(const float* __restrict__ x, const float* __restrict__ bq,
                 const float* __restrict__ W1, const float* __restrict__ b1)
{
    __shared__ float hs[4][D_];
    const int bg = blockIdx.y * 4, tid = threadIdx.x;
    #pragma unroll
    for (int i = 0; i < 8; i++) {
        const int idx = tid + i * 256;          // < 2048
        const int bb = idx >> 9, dd = idx & 511;
        const int e = (bg + bb) * D_ + dd;
        hs[bb][dd] = x[((size_t)(bg + bb) * S_ + (S_ - 1)) * D_ + dd] + bq[1024 + dd]
                   + g_hp[0][e] + g_hp[1][e] + g_hp[2][e] + g_hp[3][e];
    }
    __syncthreads();
    const int m = blockIdx.x * 256 + tid;
    float a0 = b1[m], a1 = a0, a2 = a0, a3 = a0;
    #pragma unroll 8
    for (int k = 0; k < D_; k++) {
        const float w = W1[(size_t)k * M_ + m];
        a0 = fmaf(hs[0][k], w, a0);
        a1 = fmaf(hs[1][k], w, a1);
        a2 = fmaf(hs[2][k], w, a2);
        a3 = fmaf(hs[3][k], w, a3);
    }
    g_h1[(bg + 0) * M_ + m] = fmaxf(a0, 0.f);
    g_h1[(bg + 1) * M_ + m] = fmaxf(a1, 0.f);
    g_h1[(bg + 2) * M_ + m] = fmaxf(a2, 0.f);
    g_h1[(bg + 3) * M_ + m] = fmaxf(a3, 0.f);
}

__global__ __launch_bounds__(256)
void mlp2_part_kernel(const float* __restrict__ W2)
{
    __shared__ float hs[4][512];
    const int bg = blockIdx.y * 4, kz = blockIdx.z, tid = threadIdx.x;
    const int k0 = kz * 512;
    #pragma unroll
    for (int i = 0; i < 8; i++) {
        const int idx = tid + i * 256;
        hs[idx >> 9][idx & 511] = g_h1[(bg + (idx >> 9)) * M_ + k0 + (idx & 511)];
    }
    __syncthreads();
    const int m = blockIdx.x * 256 + tid;
    float a0 = 0.f, a1 = 0.f, a2 = 0.f, a3 = 0.f;
    #pragma unroll 8
    for (int k = 0; k < 512; k++) {
        const float w = W2[(size_t)(k0 + k) * M_ + m];
        a0 = fmaf(hs[0][k], w, a0);
        a1 = fmaf(hs[1][k], w, a1);
        a2 = fmaf(hs[2][k], w, a2);
        a3 = fmaf(hs[3][k], w, a3);
    }
    g_m2p[kz][(bg + 0) * M_ + m] = a0;
    g_m2p[kz][(bg + 1) * M_ + m] = a1;
    g_m2p[kz][(bg + 2) * M_ + m] = a2;
    g_m2p[kz][(bg + 3) * M_ + m] = a3;
}

// mlp2 reduce + relu + mlp3 dot, fused: warp w = batch w
__global__ void mlp3_kernel(const float* __restrict__ b2,
                            const float* __restrict__ W3,
                            const float* __restrict__ b3,
                            float* __restrict__ out)
{
    const int w = threadIdx.x >> 5, lane = threadIdx.x & 31;
    float acc = 0.f;
    #pragma unroll
    for (int i = 0; i < M_ / 32; i++) {
        const int m = lane + i * 32;
        const int e = w * M_ + m;
        float v = b2[m] + g_m2p[0][e] + g_m2p[1][e] + g_m2p[2][e] + g_m2p[3][e];
        acc = fmaf(fmaxf(v, 0.f), W3[m], acc);
    }
    #pragma unroll
    for (int off = 16; off; off >>= 1) acc += __shfl_xor_sync(0xffffffffu, acc, off);
    if (lane == 0) out[w] = acc + b3[0];
}

// ---------------------------------------------------------------------------
// Entry. Output layout: (out, q, k) flat: [0,16) out, then q, then k.
// ---------------------------------------------------------------------------
extern "C" void kernel_launch(void* const* d_in, const int* in_sizes, int n_in,
                              void* d_out, int out_size)
{
    const float* x     = (const float*)d_in[0];
    const float* W_qkv = (const float*)d_in[1];
    const float* b_qkv = (const float*)d_in[2];
    const float* W1    = (const float*)d_in[3];
    const float* b1    = (const float*)d_in[4];
    const float* W2    = (const float*)d_in[5];
    const float* b2    = (const float*)d_in[6];
    const float* W3    = (const float*)d_in[7];
    const float* b3    = (const float*)d_in[8];

    float* out   = (float*)d_out;
    float* q_out = out + 16;
    float* k_out = out + 16 + (size_t)NROWS * D_;

    cudaFuncSetAttribute(qk_mma, cudaFuncAttributeMaxDynamicSharedMemorySize, QKV_SMEM);

    qlast_part_kernel<<<dim3(4, B_), 512>>>(x, W_qkv);              // 1
    u_kernel<<<dim3(D_ / 8, B_), 256>>>(W_qkv, b_qkv);              // 2
    scores_cvt_kernel<<<NROWS / 8, 256>>>(x, W_qkv);                // 3
    qk_mma<<<dim3(NQK / TN, NROWS / TM), 256, QKV_SMEM>>>(b_qkv, q_out, k_out); // 4 (ncu)
    y_part_kernel<<<dim3(B_, 32), 512>>>(x);                        // 5
    h_part_kernel<<<dim3(4, B_), 512>>>(W_qkv);                     // 6
    mlp1_kernel<<<dim3(M_ / 256, B_ / 4), 256>>>(x, b_qkv, W1, b1); // 7
    mlp2_part_kernel<<<dim3(M_ / 256, B_ / 4, 4), 256>>>(W2);       // 8
    mlp3_kernel<<<1, 512>>>(b2, W3, b3, out);                       // 9
}

// round 17
// speedup vs baseline: 1.2511x; 1.0300x over previous
#include <cuda_runtime.h>
#include <cuda_fp16.h>
#include <cstdint>

// Problem dims
constexpr int B_ = 16, S_ = 4096, D_ = 512, M_ = 2048;
constexpr int NROWS = B_ * S_;   // 65536
constexpr int NQK   = 2 * D_;    // 1024 (q and k only; v never materialized)

// ---------------------------------------------------------------------------
// Scratch (device globals: no allocations allowed)
// ---------------------------------------------------------------------------
__device__ __half g_xh[(size_t)NROWS * D_];        // x in fp16
__device__ __half g_wh[(size_t)NQK * D_];          // W_qk^T fp16 [n][k]
__device__ float g_qlp[4][B_ * D_];                // q_last k-split partials
__device__ float g_u[B_ * D_];                     // W_k @ q_last
__device__ float g_c[B_];                          // q_last . b_k
__device__ float g_scores[NROWS];
__device__ float g_part[B_ * 32 * D_];             // y chunk partials (unnorm)
__device__ float g_cmx[B_ * 32];                   // chunk max
__device__ float g_csum[B_ * 32];                  // chunk sum(exp)
__device__ float g_hp[4][B_ * D_];                 // h k-split partials
__device__ float g_h1[B_ * M_];
__device__ float g_m2p[4][B_ * M_];                // mlp2 k-split partials

// ---------------------------------------------------------------------------
// Helpers (baseline PTX: ldmatrix / mma.sync / cp.async — sm_80+)
// ---------------------------------------------------------------------------
__device__ __forceinline__ uint32_t smem_u32(const void* p) {
    uint32_t a;
    asm("{ .reg .u64 t; cvta.to.shared.u64 t, %1; cvt.u32.u64 %0, t; }"
        : "=r"(a) : "l"(p));
    return a;
}

// Swizzle<3,4,3> for 128-byte rows: bits[6:4] ^= bits[9:7]
#define SWZ128(o) ((o) ^ ((((uint32_t)(o)) >> 3) & 0x70u))

__device__ __forceinline__ void cp_async16(uint32_t sdst, const void* gsrc) {
    asm volatile("cp.async.cg.shared.global [%0], [%1], 16;"
                 :: "r"(sdst), "l"(gsrc) : "memory");
}
#define CP_COMMIT() asm volatile("cp.async.commit_group;" ::: "memory")
#define CP_WAIT(n)  asm volatile("cp.async.wait_group %0;" :: "n"(n) : "memory")

__device__ __forceinline__ void ldm_x4(uint32_t* r, uint32_t addr) {
    asm volatile("ldmatrix.sync.aligned.m8n8.x4.shared.b16 {%0,%1,%2,%3}, [%4];"
                 : "=r"(r[0]), "=r"(r[1]), "=r"(r[2]), "=r"(r[3]) : "r"(addr));
}

__device__ __forceinline__ void mma_f32acc(float* c, const uint32_t* a, const uint32_t* b) {
    asm volatile(
        "mma.sync.aligned.m16n8k16.row.col.f32.f16.f16.f32 "
        "{%0,%1,%2,%3}, {%4,%5,%6,%7}, {%8,%9}, {%0,%1,%2,%3};"
        : "+f"(c[0]), "+f"(c[1]), "+f"(c[2]), "+f"(c[3])
        : "r"(a[0]), "r"(a[1]), "r"(a[2]), "r"(a[3]), "r"(b[0]), "r"(b[1]));
}

// ---------------------------------------------------------------------------
// qlast partials: grid (4, B)
// ---------------------------------------------------------------------------
__global__ __launch_bounds__(512)
void qlast_part_kernel(const float* __restrict__ x, const float* __restrict__ W)
{
    __shared__ float xs[128];
    const int kz = blockIdx.x, b = blockIdx.y, d = threadIdx.x;
    const int k0 = kz * 128;

    if (d < 128) xs[d] = x[((size_t)b * S_ + (S_ - 1)) * D_ + k0 + d];
    __syncthreads();

    float acc = 0.f;
    #pragma unroll 8
    for (int j = 0; j < 128; j++)
        acc = fmaf(xs[j], W[(size_t)(k0 + j) * 1536 + d], acc);
    g_qlp[kz][b * D_ + d] = acc;
}

// u[b][j] = W_k[j,:] . q_last[b] — warp per j (1024 blocks).
__global__ __launch_bounds__(256)
void u_kernel(const float* __restrict__ W, const float* __restrict__ bq)
{
    __shared__ float qs[D_];
    __shared__ float red[256];
    const int b = blockIdx.y, tid = threadIdx.x;
    const int warp = tid >> 5, lane = tid & 31;

    #pragma unroll
    for (int h = 0; h < 2; h++) {
        const int i = tid + h * 256;
        qs[i] = bq[i] + g_qlp[0][b * D_ + i] + g_qlp[1][b * D_ + i]
                      + g_qlp[2][b * D_ + i] + g_qlp[3][b * D_ + i];
    }
    __syncthreads();

    if (blockIdx.x == 0) {
        red[tid] = qs[tid] * bq[512 + tid] + qs[tid + 256] * bq[512 + tid + 256];
        __syncthreads();
        for (int s = 128; s; s >>= 1) {
            if (tid < s) red[tid] += red[tid + s];
            __syncthreads();
        }
        if (tid == 0) g_c[b] = red[0];
    }

    const int j = blockIdx.x * 8 + warp;
    const float* wrow = W + (size_t)j * 1536 + 512;
    float acc = 0.f;
    #pragma unroll
    for (int i = 0; i < 16; i++)
        acc = fmaf(wrow[lane + i * 32], qs[lane + i * 32], acc);
    #pragma unroll
    for (int off = 16; off; off >>= 1) acc += __shfl_xor_sync(0xffffffffu, acc, off);
    if (lane == 0) g_u[b * D_ + j] = acc;
}

// ---------------------------------------------------------------------------
// scores + x->fp16 + W->fp16 fusion
// ---------------------------------------------------------------------------
__global__ void scores_cvt_kernel(const float* __restrict__ x,
                                  const float* __restrict__ W)
{
    const int gtid = blockIdx.x * 256 + threadIdx.x;
    if (gtid < D_ * NQK) {
        const int k = gtid >> 10, n = gtid & 1023;
        g_wh[(size_t)n * D_ + k] = __float2half_rn(W[(size_t)k * 1536 + n]);
    }

    const int gw   = (blockIdx.x * blockDim.x + threadIdx.x) >> 5;
    const int lane = threadIdx.x & 31;
    const int b    = gw >> 12;

    const float4* ur = (const float4*)(g_u + b * D_);
    const float4* xr = (const float4*)(x + (size_t)gw * D_);
    __half2* xo = (__half2*)(g_xh + (size_t)gw * D_);

    float acc = 0.f;
    #pragma unroll
    for (int it = 0; it < 4; it++) {
        const int e4 = lane + it * 32;
        float4 uv = ur[e4];
        float4 xv = xr[e4];
        acc += uv.x * xv.x + uv.y * xv.y + uv.z * xv.z + uv.w * xv.w;
        __half2 h0 = __halves2half2(__float2half_rn(xv.x), __float2half_rn(xv.y));
        __half2 h1 = __halves2half2(__float2half_rn(xv.z), __float2half_rn(xv.w));
        xo[e4 * 2]     = h0;
        xo[e4 * 2 + 1] = h1;
    }
    #pragma unroll
    for (int off = 16; off; off >>= 1) acc += __shfl_xor_sync(0xffffffffu, acc, off);
    if (lane == 0) g_scores[gw] = acc + g_c[b];
}

// ---------------------------------------------------------------------------
// FUSED: QK GEMM (blocks 0..4095) + y_part online-softmax (blocks 4096..4607).
// The y blocks are scheduled last and absorb the GEMM's drain waves.
// GEMM: CTA 128x128, warp 64x32, TK=64, 3-stage cp.async, 96KB smem.
// ---------------------------------------------------------------------------
constexpr int TM = 128, TN = 128, TK = 64;
constexpr int NCHUNK = D_ / TK;  // 8
constexpr int A_TILE = 128 * 128;
constexpr int B_TILE = 128 * 128;
constexpr int OFF_AH = 0;
constexpr int OFF_BH = OFF_AH + A_TILE;
constexpr int STAGE_BYTES = OFF_BH + B_TILE;           // 32 KB
constexpr int QKV_SMEM    = 3 * STAGE_BYTES;           // 96 KB dynamic
constexpr int GEMM_BLOCKS = (NQK / TN) * (NROWS / TM); // 4096
constexpr int Y_BLOCKS    = B_ * 32;                   // 512

__global__ __launch_bounds__(256, 2)
void qk_mma(const float* __restrict__ bias,
            float* __restrict__ q_out, float* __restrict__ k_out,
            const float* __restrict__ x)
{
    extern __shared__ __align__(128) uint8_t sm[];
    const int tid = threadIdx.x;

    if (blockIdx.x >= GEMM_BLOCKS) {
        // ---- y_part branch: online softmax chunk partials ----
        float* ss = (float*)sm;                 // 128 floats
        const int r = blockIdx.x - GEMM_BLOCKS;
        const int b = r >> 5, ch = r & 31;

        if (tid < 128) ss[tid] = g_scores[(size_t)b * S_ + ch * 128 + tid];
        __syncthreads();

        float mx = -1e30f;
        #pragma unroll 16
        for (int s = 0; s < 128; s++) mx = fmaxf(mx, ss[s]);

        const int d0 = tid, d1 = tid + 256;
        const float* xp = x + ((size_t)b * S_ + ch * 128) * D_;
        float a0 = 0.f, a1 = 0.f, lsum = 0.f;
        #pragma unroll 4
        for (int s = 0; s < 128; s++) {
            const float e = expf(ss[s] - mx);
            lsum += e;
            a0 = fmaf(e, xp[(size_t)s * D_ + d0], a0);
            a1 = fmaf(e, xp[(size_t)s * D_ + d1], a1);
        }
        g_part[(b * 32 + ch) * D_ + d0] = a0;
        g_part[(b * 32 + ch) * D_ + d1] = a1;
        if (tid == 0) { g_cmx[b * 32 + ch] = mx; g_csum[b * 32 + ch] = lsum; }
        return;
    }

    // ---- GEMM branch ----
    const uint32_t sb = smem_u32(sm);
    const int warp = tid >> 5, lane = tid & 31;
    const int n0 = (blockIdx.x & 7) * TN;
    const int m0 = (blockIdx.x >> 3) * TM;
    const int wm = (warp & 1) * 64;
    const int wn = (warp >> 1) * 32;

    const int rl = tid >> 3;
    const int cl = tid & 7;

    auto load_stage = [&](int stage, int ch) {
        const uint32_t s0 = sb + stage * STAGE_BYTES;
        const int kcol = ch * TK + cl * 8;
        #pragma unroll
        for (int j = 0; j < 4; j++) {
            const int row = rl + j * 32;
            const uint32_t so = SWZ128((uint32_t)row * 128 + cl * 16);
            cp_async16(s0 + OFF_AH + so, g_xh + (size_t)(m0 + row) * D_ + kcol);
            cp_async16(s0 + OFF_BH + so, g_wh + (size_t)(n0 + row) * D_ + kcol);
        }
    };

    float acc[4][4][4];
    #pragma unroll
    for (int i = 0; i < 4; i++)
        #pragma unroll
        for (int j = 0; j < 4; j++)
            #pragma unroll
            for (int e = 0; e < 4; e++) acc[i][j][e] = 0.f;

    const uint32_t a_row = (lane & 15);
    const uint32_t a_byt = (lane >> 4) << 4;
    const uint32_t b_row = ((lane >> 4) << 3) + (lane & 7);
    const uint32_t b_byt = ((lane >> 3) & 1) << 4;

    load_stage(0, 0); CP_COMMIT();
    load_stage(1, 1); CP_COMMIT();

    for (int ch = 0; ch < NCHUNK; ch++) {
        if (ch + 2 < NCHUNK) {
            load_stage((ch + 2) % 3, ch + 2); CP_COMMIT();
            CP_WAIT(2);
        } else {
            CP_WAIT(0);
        }
        __syncthreads();

        const uint32_t s0 = sb + (ch % 3) * STAGE_BYTES;

        #pragma unroll
        for (int kk = 0; kk < 4; kk++) {
            uint32_t ah[4][4];
            #pragma unroll
            for (int mf = 0; mf < 4; mf++) {
                const uint32_t ra = SWZ128((uint32_t)(wm + mf * 16 + a_row) * 128
                                           + kk * 32 + a_byt);
                ldm_x4(ah[mf], s0 + OFF_AH + ra);
            }
            uint32_t bh[4][2];
            #pragma unroll
            for (int p = 0; p < 2; p++) {
                const uint32_t rb = SWZ128((uint32_t)(wn + p * 16 + b_row) * 128
                                           + kk * 32 + b_byt);
                uint32_t t[4];
                ldm_x4(t, s0 + OFF_BH + rb);
                bh[p * 2][0] = t[0]; bh[p * 2][1] = t[1];
                bh[p * 2 + 1][0] = t[2]; bh[p * 2 + 1][1] = t[3];
            }
            #pragma unroll
            for (int mf = 0; mf < 4; mf++)
                #pragma unroll
                for (int nf = 0; nf < 4; nf++) mma_f32acc(acc[mf][nf], ah[mf], bh[nf]);
        }
        __syncthreads();
    }

    const int region = n0 >> 9;
    float* dst = region ? k_out : q_out;
    const int cbase = n0 - region * 512;

    #pragma unroll
    for (int mf = 0; mf < 4; mf++) {
        #pragma unroll
        for (int nf = 0; nf < 4; nf++) {
            const int colg = n0 + wn + nf * 8 + (lane & 3) * 2;
            const float2 bv = *(const float2*)(bias + colg);
            const int col = cbase + wn + nf * 8 + (lane & 3) * 2;
            const int r0 = m0 + wm + mf * 16 + (lane >> 2);
            float2 v0 = make_float2(acc[mf][nf][0] + bv.x, acc[mf][nf][1] + bv.y);
            float2 v1 = make_float2(acc[mf][nf][2] + bv.x, acc[mf][nf][3] + bv.y);
            *(float2*)(dst + (size_t)r0 * D_ + col)       = v0;
            *(float2*)(dst + (size_t)(r0 + 8) * D_ + col) = v1;
        }
    }
}

// ---------------------------------------------------------------------------
// h partials: grid (4, B)
// ---------------------------------------------------------------------------
__global__ __launch_bounds__(512)
void h_part_kernel(const float* __restrict__ W)
{
    __shared__ float ys[128];
    const int kz = blockIdx.x, b = blockIdx.y, d = threadIdx.x;
    const int k0 = kz * 128;

    float gmx = -1e30f;
    #pragma unroll
    for (int ch = 0; ch < 32; ch++) gmx = fmaxf(gmx, g_cmx[b * 32 + ch]);
    float gsum = 0.f;
    #pragma unroll
    for (int ch = 0; ch < 32; ch++)
        gsum += g_csum[b * 32 + ch] * expf(g_cmx[b * 32 + ch] - gmx);

    if (d < 128) {
        float yy = 0.f;
        #pragma unroll
        for (int ch = 0; ch < 32; ch++) {
            const float w = expf(g_cmx[b * 32 + ch] - gmx);
            yy = fmaf(g_part[(b * 32 + ch) * D_ + k0 + d], w, yy);
        }
        ys[d] = yy / gsum;
    }
    __syncthreads();

    float acc = 0.f;
    #pragma unroll 8
    for (int j = 0; j < 128; j++)
        acc = fmaf(ys[j], W[(size_t)(k0 + j) * 1536 + 1024 + d], acc);
    g_hp[kz][b * D_ + d] = acc;
}

// ---------------------------------------------------------------------------
// MLP1: 1 batch per block (128 blocks), h combine in staging
// ---------------------------------------------------------------------------
__global__ __launch_bounds__(256)
void mlp1_kernel(const float* __restrict__ x, const float* __restrict__ bq,
                 const float* __restrict__ W1, const float* __restrict__ b1)
{
    __shared__ float hs[D_];
    const int b = blockIdx.y, tid = threadIdx.x;
    #pragma unroll
    for (int i = 0; i < 2; i++) {
        const int dd = tid + i * 256;
        const int e = b * D_ + dd;
        hs[dd] = x[((size_t)b * S_ + (S_ - 1)) * D_ + dd] + bq[1024 + dd]
               + g_hp[0][e] + g_hp[1][e] + g_hp[2][e] + g_hp[3][e];
    }
    __syncthreads();
    const int m = blockIdx.x * 256 + tid;
    float a0 = b1[m];
    #pragma unroll 8
    for (int k = 0; k < D_; k++)
        a0 = fmaf(hs[k], W1[(size_t)k * M_ + m], a0);
    g_h1[b * M_ + m] = fmaxf(a0, 0.f);
}

__global__ __launch_bounds__(256)
void mlp2_part_kernel(const float* __restrict__ W2)
{
    __shared__ float hs[4][512];
    const int bg = blockIdx.y * 4, kz = blockIdx.z, tid = threadIdx.x;
    const int k0 = kz * 512;
    #pragma unroll
    for (int i = 0; i < 8; i++) {
        const int idx = tid + i * 256;
        hs[idx >> 9][idx & 511] = g_h1[(bg + (idx >> 9)) * M_ + k0 + (idx & 511)];
    }
    __syncthreads();
    const int m = blockIdx.x * 256 + tid;
    float a0 = 0.f, a1 = 0.f, a2 = 0.f, a3 = 0.f;
    #pragma unroll 8
    for (int k = 0; k < 512; k++) {
        const float w = W2[(size_t)(k0 + k) * M_ + m];
        a0 = fmaf(hs[0][k], w, a0);
        a1 = fmaf(hs[1][k], w, a1);
        a2 = fmaf(hs[2][k], w, a2);
        a3 = fmaf(hs[3][k], w, a3);
    }
    g_m2p[kz][(bg + 0) * M_ + m] = a0;
    g_m2p[kz][(bg + 1) * M_ + m] = a1;
    g_m2p[kz][(bg + 2) * M_ + m] = a2;
    g_m2p[kz][(bg + 3) * M_ + m] = a3;
}

// mlp2 reduce + relu + mlp3 dot, fused: warp w = batch w
__global__ void mlp3_kernel(const float* __restrict__ b2,
                            const float* __restrict__ W3,
                            const float* __restrict__ b3,
                            float* __restrict__ out)
{
    const int w = threadIdx.x >> 5, lane = threadIdx.x & 31;
    float acc = 0.f;
    #pragma unroll
    for (int i = 0; i < M_ / 32; i++) {
        const int m = lane + i * 32;
        const int e = w * M_ + m;
        float v = b2[m] + g_m2p[0][e] + g_m2p[1][e] + g_m2p[2][e] + g_m2p[3][e];
        acc = fmaf(fmaxf(v, 0.f), W3[m], acc);
    }
    #pragma unroll
    for (int off = 16; off; off >>= 1) acc += __shfl_xor_sync(0xffffffffu, acc, off);
    if (lane == 0) out[w] = acc + b3[0];
}

// ---------------------------------------------------------------------------
// Entry. Output layout: (out, q, k) flat: [0,16) out, then q, then k.
// ---------------------------------------------------------------------------
extern "C" void kernel_launch(void* const* d_in, const int* in_sizes, int n_in,
                              void* d_out, int out_size)
{
    const float* x     = (const float*)d_in[0];
    const float* W_qkv = (const float*)d_in[1];
    const float* b_qkv = (const float*)d_in[2];
    const float* W1    = (const float*)d_in[3];
    const float* b1    = (const float*)d_in[4];
    const float* W2    = (const float*)d_in[5];
    const float* b2    = (const float*)d_in[6];
    const float* W3    = (const float*)d_in[7];
    const float* b3    = (const float*)d_in[8];

    float* out   = (float*)d_out;
    float* q_out = out + 16;
    float* k_out = out + 16 + (size_t)NROWS * D_;

    cudaFuncSetAttribute(qk_mma, cudaFuncAttributeMaxDynamicSharedMemorySize, QKV_SMEM);

    qlast_part_kernel<<<dim3(4, B_), 512>>>(x, W_qkv);              // 1
    u_kernel<<<dim3(D_ / 8, B_), 256>>>(W_qkv, b_qkv);              // 2
    scores_cvt_kernel<<<NROWS / 8, 256>>>(x, W_qkv);                // 3
    qk_mma<<<GEMM_BLOCKS + Y_BLOCKS, 256, QKV_SMEM>>>(b_qkv, q_out, k_out, x); // 4 (ncu)
    h_part_kernel<<<dim3(4, B_), 512>>>(W_qkv);                     // 5
    mlp1_kernel<<<dim3(M_ / 256, B_), 256>>>(x, b_qkv, W1, b1);     // 6
    mlp2_part_kernel<<<dim3(M_ / 256, B_ / 4, 4), 256>>>(W2);       // 7
    mlp3_kernel<<<1, 512>>>(b2, W3, b3, out);                       // 8
}